// round 1
// baseline (speedup 1.0000x reference)
#include <cuda_runtime.h>

#define NB   8
#define NA   9
#define NH   64
#define NW   64
#define NGT  32
#define NCLS 80
#define NN   (NA * NH * NW)   // 36864 anchors per image

// ---------------- scratch / accumulators (device globals; no allocs) ----------------
__device__ float g_xywh;              // global loss_xywh accumulator
__device__ float g_im_cls[NB];        // per-image BCE sum (before /num_pos)
__device__ int   g_num_pos[NB];       // per-image positive-anchor count
__device__ int   g_flags[NB * NN];    // per-anchor: gt_cat | pos<<8 | penalty<<9

// Anchor W/H table: for s in {1.0,1.2599,1.5874} for r in {(1,1),(1.4,0.7),(0.7,1.4)}, base=32
__constant__ float c_aw[NA] = {32.0f, 44.8f, 22.4f, 40.3168f, 56.44352f, 28.22176f,
                               50.7968f, 71.11552f, 35.55776f};
__constant__ float c_ah[NA] = {32.0f, 22.4f, 44.8f, 40.3168f, 28.22176f, 56.44352f,
                               50.7968f, 35.55776f, 71.11552f};

// ---------------- kernel 0: zero accumulators ----------------
__global__ void init_k() {
    int t = threadIdx.x;
    if (t == 0) g_xywh = 0.0f;
    if (t < NB) { g_im_cls[t] = 0.0f; g_num_pos[t] = 0; }
}

// ---------------- kernel 1: anchor<->GT matching + regression loss ----------------
__global__ __launch_bounds__(256) void match_k(
    const float4* __restrict__ t_xywh,   // [B, N, 4] as float4
    const float4* __restrict__ gtb,      // [B, NGT, 4] cxcywh as float4
    const int*    __restrict__ gtc)      // [B, NGT]
{
    __shared__ float sx0[NGT], sy0[NGT], sx1[NGT], sy1[NGT], sar[NGT];
    __shared__ float scx[NGT], scy[NGT], sw[NGT], sh[NGT];
    __shared__ int   sc[NGT];

    const int b = blockIdx.y;
    if (threadIdx.x < NGT) {
        int g = threadIdx.x;
        float4 bb = gtb[b * NGT + g];
        scx[g] = bb.x; scy[g] = bb.y; sw[g] = bb.z; sh[g] = bb.w;
        sx0[g] = bb.x - 0.5f * bb.z; sy0[g] = bb.y - 0.5f * bb.w;
        sx1[g] = bb.x + 0.5f * bb.z; sy1[g] = bb.y + 0.5f * bb.w;
        sar[g] = bb.z * bb.w;
        sc[g]  = gtc[b * NGT + g];
    }
    __syncthreads();

    const int n = blockIdx.x * 256 + threadIdx.x;      // anchor index in [0, NN)
    const int w = n & (NW - 1);
    const int h = (n >> 6) & (NH - 1);
    const int a = n >> 12;

    const float acx = ((float)w + 0.5f) * 8.0f;
    const float acy = ((float)h + 0.5f) * 8.0f;
    const float aw = c_aw[a], ah = c_ah[a];
    const float ax0 = acx - 0.5f * aw, ay0 = acy - 0.5f * ah;
    const float ax1 = acx + 0.5f * aw, ay1 = acy + 0.5f * ah;
    const float aarea = aw * ah;

    // running argmax of IoU kept as a fraction (no divisions in the hot loop)
    float bi = -1.0f, bu = 1.0f;
    int   bg = 0;
#pragma unroll
    for (int g = 0; g < NGT; ++g) {
        float dx = fminf(ax1, sx1[g]) - fmaxf(ax0, sx0[g]);
        float dy = fminf(ay1, sy1[g]) - fmaxf(ay0, sy0[g]);
        float inter = fmaxf(dx, 0.0f) * fmaxf(dy, 0.0f);
        float uni   = aarea + sar[g] - inter;
        if (inter * bu > bi * uni) { bi = inter; bu = uni; bg = g; }
    }

    const bool pos = bi > 0.5f * bu;       // iou > 0.5
    const bool neg = bi < 0.4f * bu;       // iou < 0.4
    const bool pen = pos || neg;

    // regression targets (only contribute when pos)
    const float tx = __fdividef(scx[bg] - acx, aw);
    const float ty = __fdividef(scy[bg] - acy, ah);
    const float tw = __logf(__fdividef(sw[bg], aw) + 1e-8f);
    const float th = __logf(__fdividef(sh[bg], ah) + 1e-8f);

    const float4 t = t_xywh[(size_t)b * NN + n];
    const float d0 = t.x - tx, d1 = t.y - ty, d2 = t.z - tw, d3 = t.w - th;
    const float lx = pos ? fmaf(d0, d0, fmaf(d1, d1, fmaf(d2, d2, d3 * d3))) : 0.0f;

    g_flags[b * NN + n] = sc[bg] | (pos ? 256 : 0) | (pen ? 512 : 0);

    // block reduction of lx and pos-count
    float v = lx;
    int   p = pos ? 1 : 0;
#pragma unroll
    for (int o = 16; o; o >>= 1) {
        v += __shfl_down_sync(0xffffffffu, v, o);
        p += __shfl_down_sync(0xffffffffu, p, o);
    }
    __shared__ float rv[8];
    __shared__ int   rp[8];
    const int lane = threadIdx.x & 31, wid = threadIdx.x >> 5;
    if (lane == 0) { rv[wid] = v; rp[wid] = p; }
    __syncthreads();
    if (wid == 0) {
        v = (lane < 8) ? rv[lane] : 0.0f;
        p = (lane < 8) ? rp[lane] : 0;
#pragma unroll
        for (int o = 4; o; o >>= 1) {
            v += __shfl_down_sync(0xffffffffu, v, o);
            p += __shfl_down_sync(0xffffffffu, p, o);
        }
        if (lane == 0) {
            atomicAdd(&g_xywh, v);
            atomicAdd(&g_num_pos[b], p);
        }
    }
}

// ---------------- kernel 2: BCE over [B, N, 80] ----------------
__device__ __forceinline__ float bce1(float x, float t) {
    float ax = fabsf(x);
    float l  = __logf(1.0f + __expf(-ax));     // log1p(exp(-|x|)), 2 MUFU
    return fmaxf(x, 0.0f) + l - t * x;
}

__global__ __launch_bounds__(256) void bce_k(const float4* __restrict__ cls) {
    const int b = blockIdx.y;
    const int i = blockIdx.x * 256 + threadIdx.x;   // float4 index within image
    const int n = i / 20;                            // NCLS/4 = 20 float4 per anchor
    const int c = (i - n * 20) * 4;                  // class base for this float4

    const int fl = g_flags[b * NN + n];
    float s = 0.0f;
    if (fl & 512) {                                  // penalty anchor
        float4 x = cls[(size_t)b * (NN * (NCLS / 4)) + i];
        const int   gc  = fl & 255;
        const float sub = (fl & 256) ? 1.0f : 0.0f;  // positive anchor -> one-hot target
        s  = bce1(x.x, (gc == c + 0) ? sub : 0.0f);
        s += bce1(x.y, (gc == c + 1) ? sub : 0.0f);
        s += bce1(x.z, (gc == c + 2) ? sub : 0.0f);
        s += bce1(x.w, (gc == c + 3) ? sub : 0.0f);
    }

    // block reduce -> atomicAdd per image
    float v = s;
#pragma unroll
    for (int o = 16; o; o >>= 1) v += __shfl_down_sync(0xffffffffu, v, o);
    __shared__ float rv[8];
    const int lane = threadIdx.x & 31, wid = threadIdx.x >> 5;
    if (lane == 0) rv[wid] = v;
    __syncthreads();
    if (wid == 0) {
        v = (lane < 8) ? rv[lane] : 0.0f;
#pragma unroll
        for (int o = 4; o; o >>= 1) v += __shfl_down_sync(0xffffffffu, v, o);
        if (lane == 0) atomicAdd(&g_im_cls[b], v);
    }
}

// ---------------- kernel 3: finalize ----------------
__global__ void fin_k(float* __restrict__ out) {
    if (threadIdx.x == 0) {
        float s = g_xywh;
#pragma unroll
        for (int b = 0; b < NB; ++b)
            s += g_im_cls[b] / ((float)g_num_pos[b] + 1.0f);
        out[0] = s * 0.125f;   // / B, exact
    }
}

// ---------------- launcher ----------------
extern "C" void kernel_launch(void* const* d_in, const int* in_sizes, int n_in,
                              void* d_out, int out_size) {
    (void)in_sizes; (void)n_in; (void)out_size;
    const float4* t_xywh = (const float4*)d_in[0];   // [8,9,64,64,4] f32
    const float4* cls    = (const float4*)d_in[1];   // [8,9,64,64,80] f32
    const float4* gtb    = (const float4*)d_in[2];   // [8,32,4] f32
    const int*    gtc    = (const int*)d_in[3];      // [8,32] i32

    init_k<<<1, 32>>>();
    match_k<<<dim3(NN / 256, NB), 256>>>(t_xywh, gtb, gtc);
    bce_k<<<dim3((NN * (NCLS / 4)) / 256, NB), 256>>>(cls);
    fin_k<<<1, 1>>>((float*)d_out);
}

// round 3
// speedup vs baseline: 1.3505x; 1.3505x over previous
#include <cuda_runtime.h>

#define NB   8
#define NA   9
#define NH   64
#define NW   64
#define NGT  32
#define NCLS 80
#define NN   (NA * NH * NW)        // 36864 anchors per image
#define APB  256                   // anchors per block
#define NBLK ((NN / APB) * NB)     // 144 * 8 = 1152 blocks

// ---------------- accumulators (device globals; zero-init at load, self-reset) ----
__device__ float g_xywh;
__device__ float g_im_cls[NB];
__device__ int   g_num_pos[NB];
__device__ unsigned int g_tick;

// Anchor W/H table: s in {1.0,1.2599,1.5874} x r in {(1,1),(1.4,0.7),(0.7,1.4)}, base=32
__constant__ float c_aw[NA] = {32.0f, 44.8f, 22.4f, 40.3168f, 56.44352f, 28.22176f,
                               50.7968f, 71.11552f, 35.55776f};
__constant__ float c_ah[NA] = {32.0f, 22.4f, 44.8f, 40.3168f, 28.22176f, 56.44352f,
                               50.7968f, 35.55776f, 71.11552f};

__device__ __forceinline__ float bce1(float x, float t) {
    float ax = fabsf(x);
    float l  = __logf(1.0f + __expf(-ax));     // softplus(-|x|): 2 MUFU ops
    return fmaxf(x, 0.0f) + l - t * x;
}

__global__ __launch_bounds__(256) void retina_fused_k(
    const float4* __restrict__ t_xywh,   // [B, N, 4]
    const float4* __restrict__ cls,      // [B, N, 20] float4
    const float4* __restrict__ gtb,      // [B, NGT, 4] cxcywh
    const int*    __restrict__ gtc,      // [B, NGT]
    float*        __restrict__ out)
{
    __shared__ float sx0[NGT], sy0[NGT], sx1[NGT], sy1[NGT], sar[NGT];
    __shared__ float scx[NGT], scy[NGT], sw[NGT], sh[NGT];
    __shared__ int   sc[NGT];
    __shared__ int   sflags[APB];
    __shared__ float rv[8], rc[8];
    __shared__ int   rp[8];

    const int tid = threadIdx.x;
    const int b   = blockIdx.y;
    const int A0  = blockIdx.x * APB;

    if (tid < NGT) {
        float4 bb = gtb[b * NGT + tid];
        scx[tid] = bb.x; scy[tid] = bb.y; sw[tid] = bb.z; sh[tid] = bb.w;
        sx0[tid] = bb.x - 0.5f * bb.z; sy0[tid] = bb.y - 0.5f * bb.w;
        sx1[tid] = bb.x + 0.5f * bb.z; sy1[tid] = bb.y + 0.5f * bb.w;
        sar[tid] = bb.z * bb.w;
        sc[tid]  = gtc[b * NGT + tid];
    }
    __syncthreads();

    // ---------------- phase 1: match (one anchor per thread) ----------------
    const int n = A0 + tid;
    const int w = n & (NW - 1);
    const int h = (n >> 6) & (NH - 1);
    const int a = n >> 12;

    const float acx = ((float)w + 0.5f) * 8.0f;
    const float acy = ((float)h + 0.5f) * 8.0f;
    const float aw = c_aw[a], ah = c_ah[a];
    const float ax0 = acx - 0.5f * aw, ay0 = acy - 0.5f * ah;
    const float ax1 = acx + 0.5f * aw, ay1 = acy + 0.5f * ah;
    const float aarea = aw * ah;

    float bi = -1.0f, bu = 1.0f;     // running argmax IoU as a fraction (no divides)
    int   bg = 0;
#pragma unroll
    for (int g = 0; g < NGT; ++g) {
        float dx = fminf(ax1, sx1[g]) - fmaxf(ax0, sx0[g]);
        float dy = fminf(ay1, sy1[g]) - fmaxf(ay0, sy0[g]);
        float inter = fmaxf(dx, 0.0f) * fmaxf(dy, 0.0f);
        float uni   = aarea + sar[g] - inter;
        if (inter * bu > bi * uni) { bi = inter; bu = uni; bg = g; }
    }

    const bool pos = bi > 0.5f * bu;
    const bool neg = bi < 0.4f * bu;
    const bool pen = pos || neg;

    const float tx = __fdividef(scx[bg] - acx, aw);
    const float ty = __fdividef(scy[bg] - acy, ah);
    const float tw = __logf(__fdividef(sw[bg], aw) + 1e-8f);
    const float th = __logf(__fdividef(sh[bg], ah) + 1e-8f);

    const float4 t = t_xywh[(size_t)b * NN + n];
    const float d0 = t.x - tx, d1 = t.y - ty, d2 = t.z - tw, d3 = t.w - th;
    float lx = pos ? fmaf(d0, d0, fmaf(d1, d1, fmaf(d2, d2, d3 * d3))) : 0.0f;
    int   pc = pos ? 1 : 0;

    sflags[tid] = sc[bg] | (pos ? 256 : 0) | (pen ? 512 : 0);
    __syncthreads();

    // ---------------- phase 2: BCE over this block's 256 anchors x 80 classes ----
    const float4* cp = cls + ((size_t)b * NN + A0) * (NCLS / 4);
    float cs = 0.0f;
#pragma unroll
    for (int j = 0; j < 20; ++j) {
        const int idx = j * APB + tid;          // float4 idx within block chunk
        const int nl  = idx / 20;
        const int cb  = (idx - nl * 20) * 4;
        const int fl  = sflags[nl];
        if (fl & 512) {
            float4 x = cp[idx];
            const int   gc  = fl & 255;
            const float sub = (fl & 256) ? 1.0f : 0.0f;
            cs += bce1(x.x, (gc == cb + 0) ? sub : 0.0f);
            cs += bce1(x.y, (gc == cb + 1) ? sub : 0.0f);
            cs += bce1(x.z, (gc == cb + 2) ? sub : 0.0f);
            cs += bce1(x.w, (gc == cb + 3) ? sub : 0.0f);
        }
    }

    // ---------------- phase 3: block reductions + last-block finalize ----------
    float v = lx, c = cs;
    int   p = pc;
#pragma unroll
    for (int o = 16; o; o >>= 1) {
        v += __shfl_down_sync(0xffffffffu, v, o);
        c += __shfl_down_sync(0xffffffffu, c, o);
        p += __shfl_down_sync(0xffffffffu, p, o);
    }
    const int lane = tid & 31, wid = tid >> 5;
    if (lane == 0) { rv[wid] = v; rc[wid] = c; rp[wid] = p; }
    __syncthreads();
    if (wid == 0) {
        v = (lane < 8) ? rv[lane] : 0.0f;
        c = (lane < 8) ? rc[lane] : 0.0f;
        p = (lane < 8) ? rp[lane] : 0;
#pragma unroll
        for (int o = 4; o; o >>= 1) {
            v += __shfl_down_sync(0xffffffffu, v, o);
            c += __shfl_down_sync(0xffffffffu, c, o);
            p += __shfl_down_sync(0xffffffffu, p, o);
        }
        if (lane == 0) {
            atomicAdd(&g_xywh, v);
            atomicAdd(&g_im_cls[b], c);
            atomicAdd(&g_num_pos[b], p);
            __threadfence();
            // self-wrapping ticket: returns old value, wraps NBLK-1 -> 0
            unsigned int old = atomicInc(&g_tick, NBLK - 1u);
            if (old == NBLK - 1u) {
                volatile float* vx = &g_xywh;
                volatile float* vc = g_im_cls;
                volatile int*   vp = g_num_pos;
                float s = *vx;
#pragma unroll
                for (int bb = 0; bb < NB; ++bb)
                    s += vc[bb] / ((float)vp[bb] + 1.0f);
                out[0] = s * 0.125f;
                __threadfence();   // order reads/out-write before resets
                *vx = 0.0f;
#pragma unroll
                for (int bb = 0; bb < NB; ++bb) { vc[bb] = 0.0f; vp[bb] = 0; }
            }
        }
    }
}

extern "C" void kernel_launch(void* const* d_in, const int* in_sizes, int n_in,
                              void* d_out, int out_size) {
    (void)in_sizes; (void)n_in; (void)out_size;
    const float4* t_xywh = (const float4*)d_in[0];
    const float4* cls    = (const float4*)d_in[1];
    const float4* gtb    = (const float4*)d_in[2];
    const int*    gtc    = (const int*)d_in[3];

    retina_fused_k<<<dim3(NN / APB, NB), 256>>>(t_xywh, cls, gtb, gtc, (float*)d_out);
}

// round 4
// speedup vs baseline: 1.9180x; 1.4202x over previous
#include <cuda_runtime.h>

#define NB   8
#define NA   9
#define NH   64
#define NW   64
#define NGT  32
#define NCLS 80
#define NN   (NA * NH * NW)        // 36864 anchors per image
#define APB  128                   // anchors per block
#define NBLK ((NN / APB) * NB)     // 288 * 8 = 2304 blocks

// ---------------- accumulators (device globals; zero-init at load, self-reset) ----
__device__ float g_xywh;
__device__ float g_im_cls[NB];
__device__ int   g_num_pos[NB];
__device__ unsigned int g_tick;

// Anchor W/H: s in {1.0,1.2599,1.5874} x r in {(1,1),(1.4,0.7),(0.7,1.4)}, base=32
__constant__ float c_aw[NA] = {32.0f, 44.8f, 22.4f, 40.3168f, 56.44352f, 28.22176f,
                               50.7968f, 71.11552f, 35.55776f};
__constant__ float c_ah[NA] = {32.0f, 22.4f, 44.8f, 40.3168f, 28.22176f, 56.44352f,
                               50.7968f, 35.55776f, 71.11552f};

#define LOG2E 1.4426950408889634f
#define LN2   0.6931471805599453f

__device__ __forceinline__ float ex2a(float x) {
    float r; asm("ex2.approx.f32 %0, %1;" : "=f"(r) : "f"(x)); return r;
}
__device__ __forceinline__ float lg2a(float x) {
    float r; asm("lg2.approx.f32 %0, %1;" : "=f"(r) : "f"(x)); return r;
}
// lg2(1 + exp(-|x|*ln2... )) piece of softplus (to be scaled by LN2)
__device__ __forceinline__ float spl_l(float x) {
    return lg2a(1.0f + ex2a(fabsf(x) * (-LOG2E)));
}
__device__ __forceinline__ float softplus_full(float x) {
    return fmaxf(x, 0.0f) + LN2 * spl_l(x);
}

__global__ __launch_bounds__(256) void retina_fused_k(
    const float4* __restrict__ t_xywh,   // [B, N, 4]
    const float4* __restrict__ cls,      // [B, N, 20] float4
    const float4* __restrict__ gtb,      // [B, NGT, 4] cxcywh
    const int*    __restrict__ gtc,      // [B, NGT]
    float*        __restrict__ out)
{
    __shared__ float4 sbox[NGT];   // (x0, y0, x1, y1)
    __shared__ float  sarea[NGT];
    __shared__ float  rv[8], rc[8];
    __shared__ int    rp[8];

    const int tid = threadIdx.x;
    const int b   = blockIdx.y;
    const int A0  = blockIdx.x * APB;

    if (tid < NGT) {
        float4 bb = gtb[b * NGT + tid];
        sbox[tid]  = make_float4(bb.x - 0.5f * bb.z, bb.y - 0.5f * bb.w,
                                 bb.x + 0.5f * bb.z, bb.y + 0.5f * bb.w);
        sarea[tid] = bb.z * bb.w;
    }

    // ---------- phase 1: dense softplus over APB anchors x 80 classes ----------
    // Sum softplus(x) for EVERY element; corrections below fix up targets/mask.
    const float4* cp = cls + ((size_t)b * NN + A0) * (NCLS / 4);
    float accR = 0.0f, accL = 0.0f;
#pragma unroll
    for (int j = 0; j < (APB * (NCLS / 4)) / 256; ++j) {   // 10 iterations
        float4 x = cp[j * 256 + tid];
        accR += fmaxf(x.x, 0.0f) + fmaxf(x.y, 0.0f)
              + fmaxf(x.z, 0.0f) + fmaxf(x.w, 0.0f);
        accL += spl_l(x.x);
        accL += spl_l(x.y);
        accL += spl_l(x.z);
        accL += spl_l(x.w);
    }
    float vcls = fmaf(LN2, accL, accR);
    float lx = 0.0f;
    int   pc = 0;
    __syncthreads();

    // ---------- phase 2: match (tid < APB, one anchor per thread) + corrections --
    if (tid < APB) {
        const int n = A0 + tid;
        const int w = n & (NW - 1);
        const int h = (n >> 6) & (NH - 1);
        const int a = n >> 12;

        const float acx = ((float)w + 0.5f) * 8.0f;
        const float acy = ((float)h + 0.5f) * 8.0f;
        const float aw = c_aw[a], ah = c_ah[a];
        const float ax0 = acx - 0.5f * aw, ay0 = acy - 0.5f * ah;
        const float ax1 = acx + 0.5f * aw, ay1 = acy + 0.5f * ah;
        const float aarea = aw * ah;

        float bi = -1.0f, bu = 1.0f;    // running argmax IoU as fraction
        int   bg = 0;
#pragma unroll
        for (int g = 0; g < NGT; ++g) {
            float4 gb = sbox[g];
            float dx = fminf(ax1, gb.z) - fmaxf(ax0, gb.x);
            float dy = fminf(ay1, gb.w) - fmaxf(ay0, gb.y);
            float inter = fmaxf(dx, 0.0f) * fmaxf(dy, 0.0f);
            float uni   = aarea + sarea[g] - inter;
            if (inter * bu > bi * uni) { bi = inter; bu = uni; bg = g; }
        }
        const bool pos = bi > 0.5f * bu;
        const bool neg = bi < 0.4f * bu;

        if (pos) {
            pc = 1;
            float4 gbb = gtb[b * NGT + bg];          // rare
            int    gc  = gtc[b * NGT + bg];
            float tx = __fdividef(gbb.x - acx, aw);
            float ty = __fdividef(gbb.y - acy, ah);
            float tw = __logf(__fdividef(gbb.z, aw) + 1e-8f);
            float th = __logf(__fdividef(gbb.w, ah) + 1e-8f);
            float4 t = t_xywh[(size_t)b * NN + n];
            float d0 = t.x - tx, d1 = t.y - ty, d2 = t.z - tw, d3 = t.w - th;
            lx = fmaf(d0, d0, fmaf(d1, d1, fmaf(d2, d2, d3 * d3)));
            // one-hot target: bce(x,1) = bce(x,0) - x  ->  subtract x[n][gc]
            const float* xp = (const float*)(cls + ((size_t)b * NN + n) * (NCLS / 4));
            vcls -= xp[gc];
        } else if (!neg) {
            // non-penalty anchor: remove its entire softplus contribution (rare)
            const float4* xp = cls + ((size_t)b * NN + n) * (NCLS / 4);
            float s = 0.0f;
#pragma unroll
            for (int j = 0; j < NCLS / 4; ++j) {
                float4 x = xp[j];
                s += softplus_full(x.x) + softplus_full(x.y)
                   + softplus_full(x.z) + softplus_full(x.w);
            }
            vcls -= s;
        }
    }

    // ---------- phase 3: block reductions + last-block finalize ----------
    float v = lx, c = vcls;
    int   p = pc;
#pragma unroll
    for (int o = 16; o; o >>= 1) {
        v += __shfl_down_sync(0xffffffffu, v, o);
        c += __shfl_down_sync(0xffffffffu, c, o);
        p += __shfl_down_sync(0xffffffffu, p, o);
    }
    const int lane = tid & 31, wid = tid >> 5;
    if (lane == 0) { rv[wid] = v; rc[wid] = c; rp[wid] = p; }
    __syncthreads();
    if (wid == 0) {
        v = (lane < 8) ? rv[lane] : 0.0f;
        c = (lane < 8) ? rc[lane] : 0.0f;
        p = (lane < 8) ? rp[lane] : 0;
#pragma unroll
        for (int o = 4; o; o >>= 1) {
            v += __shfl_down_sync(0xffffffffu, v, o);
            c += __shfl_down_sync(0xffffffffu, c, o);
            p += __shfl_down_sync(0xffffffffu, p, o);
        }
        if (lane == 0) {
            atomicAdd(&g_xywh, v);
            atomicAdd(&g_im_cls[b], c);
            atomicAdd(&g_num_pos[b], p);
            __threadfence();
            unsigned int old = atomicInc(&g_tick, NBLK - 1u);  // wraps to 0
            if (old == NBLK - 1u) {
                volatile float* vx = &g_xywh;
                volatile float* vc = g_im_cls;
                volatile int*   vp = g_num_pos;
                float s = *vx;
#pragma unroll
                for (int bb = 0; bb < NB; ++bb)
                    s += vc[bb] / ((float)vp[bb] + 1.0f);
                out[0] = s * 0.125f;
                __threadfence();
                *vx = 0.0f;
#pragma unroll
                for (int bb = 0; bb < NB; ++bb) { vc[bb] = 0.0f; vp[bb] = 0; }
            }
        }
    }
}

extern "C" void kernel_launch(void* const* d_in, const int* in_sizes, int n_in,
                              void* d_out, int out_size) {
    (void)in_sizes; (void)n_in; (void)out_size;
    const float4* t_xywh = (const float4*)d_in[0];
    const float4* cls    = (const float4*)d_in[1];
    const float4* gtb    = (const float4*)d_in[2];
    const int*    gtc    = (const int*)d_in[3];

    retina_fused_k<<<dim3(NN / APB, NB), 256>>>(t_xywh, cls, gtb, gtc, (float*)d_out);
}

// round 5
// speedup vs baseline: 2.2095x; 1.1520x over previous
#include <cuda_runtime.h>

#define NB   8
#define NA   9
#define NH   64
#define NW   64
#define NGT  32
#define NCLS 80
#define NN   (NA * NH * NW)        // 36864 anchors per image
#define APB  128                   // anchors per block (one anchor-type slab)
#define NBLK ((NN / APB) * NB)     // 288 * 8 = 2304 blocks

// ---------------- accumulators (device globals; zero-init at load, self-reset) ----
__device__ float g_xywh;
__device__ float g_im_cls[NB];
__device__ int   g_num_pos[NB];
__device__ unsigned int g_tick;

// Anchor W/H: s in {1.0,1.2599,1.5874} x r in {(1,1),(1.4,0.7),(0.7,1.4)}, base=32
__constant__ float c_aw[NA] = {32.0f, 44.8f, 22.4f, 40.3168f, 56.44352f, 28.22176f,
                               50.7968f, 71.11552f, 35.55776f};
__constant__ float c_ah[NA] = {32.0f, 22.4f, 44.8f, 40.3168f, 28.22176f, 56.44352f,
                               50.7968f, 35.55776f, 71.11552f};

#define LOG2E 1.4426950408889634f
#define LN2   0.6931471805599453f
#define R_POS 0.3333333433f        // iou>0.5  <=>  inter/(A+G) > 1/3
#define R_NEG 0.2857142985f        // iou<0.4  <=>  inter/(A+G) < 2/7

__device__ __forceinline__ float ex2a(float x) {
    float r; asm("ex2.approx.f32 %0, %1;" : "=f"(r) : "f"(x)); return r;
}
__device__ __forceinline__ float lg2a(float x) {
    float r; asm("lg2.approx.f32 %0, %1;" : "=f"(r) : "f"(x)); return r;
}
__device__ __forceinline__ float rcpa(float x) {
    float r; asm("rcp.approx.f32 %0, %1;" : "=f"(r) : "f"(x)); return r;
}
// lg2( prod_{i} (1 + 2^(x_i*log2e)) )  over one float4 -> 1 LG2 per 4 elements
__device__ __forceinline__ float quad_l(float4 x) {
    float e0 = ex2a(x.x * LOG2E);
    float e1 = ex2a(x.y * LOG2E);
    float e2 = ex2a(x.z * LOG2E);
    float e3 = ex2a(x.w * LOG2E);
    float p  = ((1.0f + e0) * (1.0f + e1)) * ((1.0f + e2) * (1.0f + e3));
    return lg2a(p);
}

__global__ __launch_bounds__(256) void retina_fused_k(
    const float4* __restrict__ t_xywh,   // [B, N, 4]
    const float4* __restrict__ cls,      // [B, N, 20] float4
    const float4* __restrict__ gtb,      // [B, NGT, 4] cxcywh
    const int*    __restrict__ gtc,      // [B, NGT]
    float*        __restrict__ out)
{
    __shared__ float4 sbox[NGT];   // (x0, y0, x1, y1)
    __shared__ float  sinv[NGT];   // 1 / (anchor_area + gt_area) for this block's 'a'
    __shared__ float  rv[8], rc[8];
    __shared__ int    rp[8];

    const int tid = threadIdx.x;
    const int b   = blockIdx.y;
    const int A0  = blockIdx.x * APB;
    const int a   = A0 >> 12;                       // anchor type, constant per block
    const float aw = c_aw[a], ah = c_ah[a];
    const float aarea = aw * ah;

    if (tid < NGT) {
        float4 bb = gtb[b * NGT + tid];
        sbox[tid] = make_float4(bb.x - 0.5f * bb.z, bb.y - 0.5f * bb.w,
                                bb.x + 0.5f * bb.z, bb.y + 0.5f * bb.w);
        sinv[tid] = rcpa(aarea + bb.z * bb.w);
    }

    // ---------- phase 1: dense Σ softplus over APB anchors x 80 classes ----------
    // softplus(x) = ln(1+e^x); batch 4 logs into one via the product identity.
    const float4* cp = cls + ((size_t)b * NN + A0) * (NCLS / 4);
    float accL = 0.0f;
#pragma unroll
    for (int j = 0; j < (APB * (NCLS / 4)) / 256; ++j) {   // 10 iterations
        accL += quad_l(cp[j * 256 + tid]);
    }
    float corr = 0.0f;     // linear-domain corrections (one-hot targets)
    float lx = 0.0f;
    int   pc = 0;
    __syncthreads();       // sbox/sinv ready

    // ---------- phase 2: match (tid < APB) + corrections ----------
    if (tid < APB) {
        const int n = A0 + tid;
        const int w = n & (NW - 1);
        const int h = (n >> 6) & (NH - 1);

        const float acx = ((float)w + 0.5f) * 8.0f;
        const float acy = ((float)h + 0.5f) * 8.0f;
        const float ax0 = acx - 0.5f * aw, ay0 = acy - 0.5f * ah;
        const float ax1 = acx + 0.5f * aw, ay1 = acy + 0.5f * ah;

        float best = 0.0f;     // r = inter/(A+G); monotone in IoU
        int   bg = 0;
#pragma unroll
        for (int g = 0; g < NGT; ++g) {
            float4 gb = sbox[g];
            float dx = fminf(ax1, gb.z) - fmaxf(ax0, gb.x);
            float dy = fminf(ay1, gb.w) - fmaxf(ay0, gb.y);
            float inter = fmaxf(dx, 0.0f) * fmaxf(dy, 0.0f);
            float r = inter * sinv[g];
            if (r > best) { best = r; bg = g; }
        }
        const bool pos = best > R_POS;
        const bool neg = best < R_NEG;

        if (pos) {
            pc = 1;
            float4 gbb = gtb[b * NGT + bg];          // rare path
            int    gc  = gtc[b * NGT + bg];
            float tx = __fdividef(gbb.x - acx, aw);
            float ty = __fdividef(gbb.y - acy, ah);
            float tw = __logf(__fdividef(gbb.z, aw) + 1e-8f);
            float th = __logf(__fdividef(gbb.w, ah) + 1e-8f);
            float4 t = t_xywh[(size_t)b * NN + n];
            float d0 = t.x - tx, d1 = t.y - ty, d2 = t.z - tw, d3 = t.w - th;
            lx = fmaf(d0, d0, fmaf(d1, d1, fmaf(d2, d2, d3 * d3)));
            // one-hot target: bce(x,1) = bce(x,0) - x  ->  subtract x[n][gc]
            const float* xp = (const float*)(cls + ((size_t)b * NN + n) * (NCLS / 4));
            corr -= xp[gc];
        } else if (!neg) {
            // non-penalty anchor (rare): remove its softplus contribution (lg2 domain)
            const float4* xp = cls + ((size_t)b * NN + n) * (NCLS / 4);
            float s = 0.0f;
#pragma unroll
            for (int j = 0; j < NCLS / 4; ++j) s += quad_l(xp[j]);
            accL -= s;
        }
    }
    float vcls = fmaf(LN2, accL, corr);

    // ---------- phase 3: block reductions + last-block finalize ----------
    float v = lx, c = vcls;
    int   p = pc;
#pragma unroll
    for (int o = 16; o; o >>= 1) {
        v += __shfl_down_sync(0xffffffffu, v, o);
        c += __shfl_down_sync(0xffffffffu, c, o);
        p += __shfl_down_sync(0xffffffffu, p, o);
    }
    const int lane = tid & 31, wid = tid >> 5;
    if (lane == 0) { rv[wid] = v; rc[wid] = c; rp[wid] = p; }
    __syncthreads();
    if (wid == 0) {
        v = (lane < 8) ? rv[lane] : 0.0f;
        c = (lane < 8) ? rc[lane] : 0.0f;
        p = (lane < 8) ? rp[lane] : 0;
#pragma unroll
        for (int o = 4; o; o >>= 1) {
            v += __shfl_down_sync(0xffffffffu, v, o);
            c += __shfl_down_sync(0xffffffffu, c, o);
            p += __shfl_down_sync(0xffffffffu, p, o);
        }
        if (lane == 0) {
            atomicAdd(&g_xywh, v);
            atomicAdd(&g_im_cls[b], c);
            atomicAdd(&g_num_pos[b], p);
            __threadfence();
            unsigned int old = atomicInc(&g_tick, NBLK - 1u);  // wraps to 0
            if (old == NBLK - 1u) {
                volatile float* vx = &g_xywh;
                volatile float* vc = g_im_cls;
                volatile int*   vp = g_num_pos;
                float s = *vx;
#pragma unroll
                for (int bb = 0; bb < NB; ++bb)
                    s += vc[bb] / ((float)vp[bb] + 1.0f);
                out[0] = s * 0.125f;
                __threadfence();
                *vx = 0.0f;
#pragma unroll
                for (int bb = 0; bb < NB; ++bb) { vc[bb] = 0.0f; vp[bb] = 0; }
            }
        }
    }
}

extern "C" void kernel_launch(void* const* d_in, const int* in_sizes, int n_in,
                              void* d_out, int out_size) {
    (void)in_sizes; (void)n_in; (void)out_size;
    const float4* t_xywh = (const float4*)d_in[0];
    const float4* cls    = (const float4*)d_in[1];
    const float4* gtb    = (const float4*)d_in[2];
    const int*    gtc    = (const int*)d_in[3];

    retina_fused_k<<<dim3(NN / APB, NB), 256>>>(t_xywh, cls, gtb, gtc, (float*)d_out);
}